// round 14
// baseline (speedup 1.0000x reference)
#include <cuda_runtime.h>
#include <stdint.h>

// AddRadiusEdgeIndex: dense [N,N] float32 mask (1.0f/0.0f),
// mask[i,j] = (||p_i - p_j|| <= 3), reference-exact fp32 rounding (rel_err==0):
//   sq  = (x*x + y*y) + z*z ; dot = fmaf(z,z',fmaf(y,y',x*x')) ;
//   d2  = fmaf(-2, dot, sq_i + sq_j) ; mask = d2 <= 9
//
// R13 -> R14: last untested knob — Blackwell 256-bit stores (st.global.v8.f32).
// Unlike R9 (two strided STG.128s per thread: 8 partial lines per warp instr),
// one STG.256 writes the warp's 1024 B fully contiguously. Store instruction
// and L1tex dispatch count halve; wavefront bytes unchanged. Expected neutral
// (confirming the LTS byte-cap floor at ~39.7 us) with small upside if L1tex
// dispatch participates in the 68% L1 utilization. Falsifier: if ptxas splits
// v8 into strided 128b stores this regresses like R9 -> revert to R13 kernel.

#define NPTS 8192
#define JPT  8     // j-points per thread = 4 packed lanes, ONE v8 store/row
#define TPB  256   // 2048 j-cols per block
#define IPB  16    // i-rows per block; grid = 4 * 512 = 2048

typedef unsigned long long u64;

__device__ __forceinline__ u64 pack2(float lo, float hi)
{
    u64 r; asm("mov.b64 %0, {%1, %2};" : "=l"(r) : "f"(lo), "f"(hi)); return r;
}
__device__ __forceinline__ u64 mul2(u64 a, u64 b)
{
    u64 r; asm("mul.rn.f32x2 %0, %1, %2;" : "=l"(r) : "l"(a), "l"(b)); return r;
}
__device__ __forceinline__ u64 add2(u64 a, u64 b)
{
    u64 r; asm("add.rn.f32x2 %0, %1, %2;" : "=l"(r) : "l"(a), "l"(b)); return r;
}
__device__ __forceinline__ u64 fma2(u64 a, u64 b, u64 c)
{
    u64 r; asm("fma.rn.f32x2 %0, %1, %2, %3;" : "=l"(r) : "l"(a), "l"(b), "l"(c)); return r;
}
__device__ __forceinline__ float set_le9(float a)
{
    float r; asm("set.le.f32.f32 %0, %1, 0f41100000;" : "=f"(r) : "f"(a)); return r;
}
__device__ __forceinline__ void stg256(float* p, const float* v)
{
    asm volatile("st.global.v8.f32 [%0], {%1,%2,%3,%4,%5,%6,%7,%8};"
                 :: "l"(p), "f"(v[0]), "f"(v[1]), "f"(v[2]), "f"(v[3]),
                    "f"(v[4]), "f"(v[5]), "f"(v[6]), "f"(v[7]) : "memory");
}

__global__ __launch_bounds__(TPB, 5)
void radius_mask_kernel(const float* __restrict__ pos, float* __restrict__ out)
{
    // per i-row, pre-packed broadcasts: [0]={x,x | y,y}  [1]={z,z | q,q}
    __shared__ ulonglong2 si2[IPB][2];

    const int t  = threadIdx.x;
    const int jb = blockIdx.x & 3;           // j-block: 4 per row-stripe
    const int ib = blockIdx.x >> 2;          // i-stripe: 512 of them
    const int i0 = ib * IPB;
    const int j0 = jb * (TPB * JPT) + t * JPT;   // multiple of 8 -> 32B aligned

    if (t < IPB) {
        const int i = i0 + t;
        float x = pos[3 * i + 0];
        float y = pos[3 * i + 1];
        float z = pos[3 * i + 2];
        float q = __fadd_rn(__fadd_rn(__fmul_rn(x, x), __fmul_rn(y, y)),
                            __fmul_rn(z, z));
        si2[t][0] = make_ulonglong2(pack2(x, x), pack2(y, y));
        si2[t][1] = make_ulonglong2(pack2(z, z), pack2(q, q));
    }

    // 8 register-resident j-points as 4 packed lanes
    u64 xj2[4], yj2[4], zj2[4], sj2[4];
#pragma unroll
    for (int g = 0; g < 4; g++) {
        float xa = pos[3 * (j0 + 2 * g) + 0];
        float ya = pos[3 * (j0 + 2 * g) + 1];
        float za = pos[3 * (j0 + 2 * g) + 2];
        float xb = pos[3 * (j0 + 2 * g + 1) + 0];
        float yb = pos[3 * (j0 + 2 * g + 1) + 1];
        float zb = pos[3 * (j0 + 2 * g + 1) + 2];
        float qa = __fadd_rn(__fadd_rn(__fmul_rn(xa, xa), __fmul_rn(ya, ya)),
                             __fmul_rn(za, za));
        float qb = __fadd_rn(__fadd_rn(__fmul_rn(xb, xb), __fmul_rn(yb, yb)),
                             __fmul_rn(zb, zb));
        xj2[g] = pack2(xa, xb);
        yj2[g] = pack2(ya, yb);
        zj2[g] = pack2(za, zb);
        sj2[g] = pack2(qa, qb);
    }

    __syncthreads();

    const u64 NEG2 = 0xC0000000C0000000ull;   // {-2.0f, -2.0f}

    float* dst = out + (size_t)i0 * NPTS + j0;

#pragma unroll
    for (int ii = 0; ii < IPB; ii++) {
        const ulonglong2 A = si2[ii][0];      // {xx, yy}  LDS.128 broadcast
        const ulonglong2 B = si2[ii][1];      // {zz, qq}

        float v[JPT];
#pragma unroll
        for (int g = 0; g < 4; g++) {
            u64 dot = fma2(zj2[g], B.x, fma2(yj2[g], A.y, mul2(xj2[g], A.x)));
            u64 d2  = fma2(NEG2, dot, add2(B.y, sj2[g]));
            float lo, hi;
            asm("mov.b64 {%0, %1}, %2;" : "=f"(lo), "=f"(hi) : "l"(d2));
            v[2 * g + 0] = set_le9(lo);
            v[2 * g + 1] = set_le9(hi);
        }
        stg256(dst, v);        // one STG.256: warp writes 1024 B contiguous
        dst += NPTS;
    }
}

extern "C" void kernel_launch(void* const* d_in, const int* in_sizes, int n_in,
                              void* d_out, int out_size)
{
    const float* pos = (const float*)d_in[0];
    float* out = (float*)d_out;
    radius_mask_kernel<<<(NPTS / (TPB * JPT)) * (NPTS / IPB), TPB>>>(pos, out);
}

// round 15
// speedup vs baseline: 1.2429x; 1.2429x over previous
#include <cuda_runtime.h>
#include <stdint.h>

// AddRadiusEdgeIndex — FINAL (converged config; 39.49-40.29 us kernel time
// reproduced across R10-R13; rel_err == 0 in every passing round).
//
// Dense [N,N] float32 mask (1.0f/0.0f), mask[i,j] = (||p_i - p_j|| <= 3),
// reference-exact fp32 rounding:
//   sq  = (x*x + y*y) + z*z                       (plain rn mul/add)
//   dot = fmaf(z,z', fmaf(y,y', x*x'))            (gemm k-loop fma chain)
//   d2  = fmaf(-2, dot, sq_i + sq_j)              (2*dot exact)
//   mask = d2 <= 9                                (max(d2,0) clamp irrelevant)
//
// Limiting resource (11 experimental rounds): chip-wide L2/LTS write-path
// throughput. 268.4 MB output / 39.7 us = 6.8 TB/s through LTS; issue 25%,
// fma 23%, occ 66%, DRAM 66% all slack. Store-grain sweep settled it:
//   STG.128 @16B/thread lane-contiguous : 39.7 us  <- floor (this kernel)
//   STG.256 @32B/thread (R14)           : 51.4 us
//   TMA bulk drain (R6)                 : 61.4 us
//   2x STG.128 @32B stride (R9)         : 73.1 us
// Other proven requirements: >=4 resident CTAs/SM (R2: 1 CTA -> 101 us).
// Tested-neutral: instr count (f32x2 halved it, no change), wave count,
// L2 eviction policies, st.global.cs hints.

#define NPTS 8192
#define JPT  4     // j-points per thread (= 2 packed lanes), one STG.128/row
#define TPB  256   // 1024 j-cols per block
#define IPB  16    // i-rows per block; grid = 8 * 512 = 4096

typedef unsigned long long u64;

__device__ __forceinline__ u64 pack2(float lo, float hi)
{
    u64 r; asm("mov.b64 %0, {%1, %2};" : "=l"(r) : "f"(lo), "f"(hi)); return r;
}
__device__ __forceinline__ u64 mul2(u64 a, u64 b)
{
    u64 r; asm("mul.rn.f32x2 %0, %1, %2;" : "=l"(r) : "l"(a), "l"(b)); return r;
}
__device__ __forceinline__ u64 add2(u64 a, u64 b)
{
    u64 r; asm("add.rn.f32x2 %0, %1, %2;" : "=l"(r) : "l"(a), "l"(b)); return r;
}
__device__ __forceinline__ u64 fma2(u64 a, u64 b, u64 c)
{
    u64 r; asm("fma.rn.f32x2 %0, %1, %2, %3;" : "=l"(r) : "l"(a), "l"(b), "l"(c)); return r;
}
__device__ __forceinline__ float set_le9(float a)
{
    float r; asm("set.le.f32.f32 %0, %1, 0f41100000;" : "=f"(r) : "f"(a)); return r;
}

__global__ __launch_bounds__(TPB, 6)
void radius_mask_kernel(const float* __restrict__ pos, float4* __restrict__ out)
{
    // per i-row, pre-packed broadcasts: [0]={x,x | y,y}  [1]={z,z | q,q}
    __shared__ ulonglong2 si2[IPB][2];

    const int t  = threadIdx.x;
    const int jb = blockIdx.x & 7;          // j-block: 8 per row-stripe
    const int ib = blockIdx.x >> 3;         // i-stripe: 512 of them
    const int i0 = ib * IPB;
    const int j0 = jb * (TPB * JPT) + t * JPT;

    if (t < IPB) {
        const int i = i0 + t;
        float x = pos[3 * i + 0];
        float y = pos[3 * i + 1];
        float z = pos[3 * i + 2];
        float q = __fadd_rn(__fadd_rn(__fmul_rn(x, x), __fmul_rn(y, y)),
                            __fmul_rn(z, z));
        si2[t][0] = make_ulonglong2(pack2(x, x), pack2(y, y));
        si2[t][1] = make_ulonglong2(pack2(z, z), pack2(q, q));
    }

    // 4 register-resident j-points as 2 packed lanes
    u64 xj2[2], yj2[2], zj2[2], sj2[2];
#pragma unroll
    for (int g = 0; g < 2; g++) {
        float xa = pos[3 * (j0 + 2 * g) + 0];
        float ya = pos[3 * (j0 + 2 * g) + 1];
        float za = pos[3 * (j0 + 2 * g) + 2];
        float xb = pos[3 * (j0 + 2 * g + 1) + 0];
        float yb = pos[3 * (j0 + 2 * g + 1) + 1];
        float zb = pos[3 * (j0 + 2 * g + 1) + 2];
        float qa = __fadd_rn(__fadd_rn(__fmul_rn(xa, xa), __fmul_rn(ya, ya)),
                             __fmul_rn(za, za));
        float qb = __fadd_rn(__fadd_rn(__fmul_rn(xb, xb), __fmul_rn(yb, yb)),
                             __fmul_rn(zb, zb));
        xj2[g] = pack2(xa, xb);
        yj2[g] = pack2(ya, yb);
        zj2[g] = pack2(za, zb);
        sj2[g] = pack2(qa, qb);
    }

    __syncthreads();

    const u64 NEG2 = 0xC0000000C0000000ull;   // {-2.0f, -2.0f}

    float4* dst = out + (size_t)i0 * (NPTS / 4) + (j0 >> 2);

#pragma unroll
    for (int ii = 0; ii < IPB; ii++) {
        const ulonglong2 A = si2[ii][0];      // {xx, yy}  LDS.128 broadcast
        const ulonglong2 B = si2[ii][1];      // {zz, qq}

        float v[JPT];
#pragma unroll
        for (int g = 0; g < 2; g++) {
            u64 dot = fma2(zj2[g], B.x, fma2(yj2[g], A.y, mul2(xj2[g], A.x)));
            u64 d2  = fma2(NEG2, dot, add2(B.y, sj2[g]));
            float lo, hi;
            asm("mov.b64 {%0, %1}, %2;" : "=f"(lo), "=f"(hi) : "l"(d2));
            v[2 * g + 0] = set_le9(lo);
            v[2 * g + 1] = set_le9(hi);
        }
        *dst = make_float4(v[0], v[1], v[2], v[3]);
        dst += NPTS / 4;
    }
}

extern "C" void kernel_launch(void* const* d_in, const int* in_sizes, int n_in,
                              void* d_out, int out_size)
{
    const float* pos = (const float*)d_in[0];
    float4* out = (float4*)d_out;
    radius_mask_kernel<<<(NPTS / (TPB * JPT)) * (NPTS / IPB), TPB>>>(pos, out);
}

// round 16
// speedup vs baseline: 1.2438x; 1.0008x over previous
#include <cuda_runtime.h>
#include <stdint.h>

// AddRadiusEdgeIndex — FINAL (converged config; 39.23-40.29 us kernel time
// reproduced five times, R10-R15; rel_err == 0 in every passing round).
//
// Dense [N,N] float32 mask (1.0f/0.0f), mask[i,j] = (||p_i - p_j|| <= 3),
// reference-exact fp32 rounding:
//   sq  = (x*x + y*y) + z*z                       (plain rn mul/add)
//   dot = fmaf(z,z', fmaf(y,y', x*x'))            (gemm k-loop fma chain)
//   d2  = fmaf(-2, dot, sq_i + sq_j)              (2*dot exact)
//   mask = d2 <= 9                                (max(d2,0) clamp irrelevant)
//
// Limiting resource (12 experimental rounds): chip-wide L2/LTS write-path
// throughput. 268.4 MB output / 39.2 us = 6.84 TB/s through LTS; issue 25%,
// fma 23%, occ 66%, DRAM 67% all slack. Store-grain sweep:
//   STG.128 @16B/thread lane-contiguous : 39.2 us  <- floor (this kernel)
//   STG.256 @32B/thread (R14)           : 51.4 us
//   TMA bulk drain (R6)                 : 61.4 us
//   2x STG.128 @32B stride (R9)         : 73.1 us
// Also required: >=4 resident CTAs/SM (R2: 1 CTA -> 101 us). Tested-neutral:
// instr count (f32x2 halved it, no change), waves, L2 policies, cs hints.

#define NPTS 8192
#define JPT  4     // j-points per thread (= 2 packed lanes), one STG.128/row
#define TPB  256   // 1024 j-cols per block
#define IPB  16    // i-rows per block; grid = 8 * 512 = 4096

typedef unsigned long long u64;

__device__ __forceinline__ u64 pack2(float lo, float hi)
{
    u64 r; asm("mov.b64 %0, {%1, %2};" : "=l"(r) : "f"(lo), "f"(hi)); return r;
}
__device__ __forceinline__ u64 mul2(u64 a, u64 b)
{
    u64 r; asm("mul.rn.f32x2 %0, %1, %2;" : "=l"(r) : "l"(a), "l"(b)); return r;
}
__device__ __forceinline__ u64 add2(u64 a, u64 b)
{
    u64 r; asm("add.rn.f32x2 %0, %1, %2;" : "=l"(r) : "l"(a), "l"(b)); return r;
}
__device__ __forceinline__ u64 fma2(u64 a, u64 b, u64 c)
{
    u64 r; asm("fma.rn.f32x2 %0, %1, %2, %3;" : "=l"(r) : "l"(a), "l"(b), "l"(c)); return r;
}
__device__ __forceinline__ float set_le9(float a)
{
    float r; asm("set.le.f32.f32 %0, %1, 0f41100000;" : "=f"(r) : "f"(a)); return r;
}

__global__ __launch_bounds__(TPB, 6)
void radius_mask_kernel(const float* __restrict__ pos, float4* __restrict__ out)
{
    // per i-row, pre-packed broadcasts: [0]={x,x | y,y}  [1]={z,z | q,q}
    __shared__ ulonglong2 si2[IPB][2];

    const int t  = threadIdx.x;
    const int jb = blockIdx.x & 7;          // j-block: 8 per row-stripe
    const int ib = blockIdx.x >> 3;         // i-stripe: 512 of them
    const int i0 = ib * IPB;
    const int j0 = jb * (TPB * JPT) + t * JPT;

    if (t < IPB) {
        const int i = i0 + t;
        float x = pos[3 * i + 0];
        float y = pos[3 * i + 1];
        float z = pos[3 * i + 2];
        float q = __fadd_rn(__fadd_rn(__fmul_rn(x, x), __fmul_rn(y, y)),
                            __fmul_rn(z, z));
        si2[t][0] = make_ulonglong2(pack2(x, x), pack2(y, y));
        si2[t][1] = make_ulonglong2(pack2(z, z), pack2(q, q));
    }

    // 4 register-resident j-points as 2 packed lanes
    u64 xj2[2], yj2[2], zj2[2], sj2[2];
#pragma unroll
    for (int g = 0; g < 2; g++) {
        float xa = pos[3 * (j0 + 2 * g) + 0];
        float ya = pos[3 * (j0 + 2 * g) + 1];
        float za = pos[3 * (j0 + 2 * g) + 2];
        float xb = pos[3 * (j0 + 2 * g + 1) + 0];
        float yb = pos[3 * (j0 + 2 * g + 1) + 1];
        float zb = pos[3 * (j0 + 2 * g + 1) + 2];
        float qa = __fadd_rn(__fadd_rn(__fmul_rn(xa, xa), __fmul_rn(ya, ya)),
                             __fmul_rn(za, za));
        float qb = __fadd_rn(__fadd_rn(__fmul_rn(xb, xb), __fmul_rn(yb, yb)),
                             __fmul_rn(zb, zb));
        xj2[g] = pack2(xa, xb);
        yj2[g] = pack2(ya, yb);
        zj2[g] = pack2(za, zb);
        sj2[g] = pack2(qa, qb);
    }

    __syncthreads();

    const u64 NEG2 = 0xC0000000C0000000ull;   // {-2.0f, -2.0f}

    float4* dst = out + (size_t)i0 * (NPTS / 4) + (j0 >> 2);

#pragma unroll
    for (int ii = 0; ii < IPB; ii++) {
        const ulonglong2 A = si2[ii][0];      // {xx, yy}  LDS.128 broadcast
        const ulonglong2 B = si2[ii][1];      // {zz, qq}

        float v[JPT];
#pragma unroll
        for (int g = 0; g < 2; g++) {
            u64 dot = fma2(zj2[g], B.x, fma2(yj2[g], A.y, mul2(xj2[g], A.x)));
            u64 d2  = fma2(NEG2, dot, add2(B.y, sj2[g]));
            float lo, hi;
            asm("mov.b64 {%0, %1}, %2;" : "=f"(lo), "=f"(hi) : "l"(d2));
            v[2 * g + 0] = set_le9(lo);
            v[2 * g + 1] = set_le9(hi);
        }
        *dst = make_float4(v[0], v[1], v[2], v[3]);
        dst += NPTS / 4;
    }
}

extern "C" void kernel_launch(void* const* d_in, const int* in_sizes, int n_in,
                              void* d_out, int out_size)
{
    const float* pos = (const float*)d_in[0];
    float4* out = (float4*)d_out;
    radius_mask_kernel<<<(NPTS / (TPB * JPT)) * (NPTS / IPB), TPB>>>(pos, out);
}